// round 5
// baseline (speedup 1.0000x reference)
#include <cuda_runtime.h>
#include <cstdint>
#include <cstddef>
#include <algorithm>

// ---------------- problem constants ----------------
#define BB   256        // batch
#define FD   128        // feature dim (also E)
#define DEG  64         // max degree
#define S1N  (BB * 50)  // 12800 rows per chain at hop-1
#define M1   (2 * S1N)  // 25600 rows (both chains) for the big GEMM

// 1 = modern JAX (threefry_partitionable default True, fold-like split,
//     32-bit bits = v0 ^ v1).  0 = legacy original threefry scheme.
#define JAX_PARTITIONABLE 1

// ---------------- device scratch (static, no runtime alloc) ----------------
__device__ int   g_s1[2][S1N];
__device__ float g_agg1[(size_t)M1 * 384];      // hop1 agg   (39.3 MB)
__device__ float g_h1  [(size_t)M1 * 128];      // hop1 hidden
__device__ float g_agg0[(size_t)2 * BB * 384];  // hop0 agg
__device__ float g_h0  [(size_t)2 * BB * 128];  // hop0 hidden
__device__ float g_aggL1[(size_t)2 * BB * 384]; // layer-1 agg
__device__ float g_head[3][(size_t)2 * BB * 128]; // mean/std/pi hidden, chains stacked

struct ColsParam {
    int out25[2][25];
    int in25 [2][25];
    int out10[2][10];
    int in10 [2][10];
};

// ---------------- host-side JAX threefry reproduction ----------------
namespace {

struct KeyPair { uint32_t a, b; };

static inline uint32_t rotl32(uint32_t x, int d) { return (x << d) | (x >> (32 - d)); }

// Standard JAX threefry2x32 block cipher (20 rounds, key injections 1..5).
static void tf2x32(uint32_t k0, uint32_t k1, uint32_t x0, uint32_t x1,
                   uint32_t& o0, uint32_t& o1) {
    const uint32_t ks2 = k0 ^ k1 ^ 0x1BD11BDAu;
    const int ra[4] = {13, 15, 26, 6};
    const int rb[4] = {17, 29, 16, 24};
    x0 += k0; x1 += k1;
    for (int i = 0; i < 4; i++) { x0 += x1; x1 = rotl32(x1, ra[i]); x1 ^= x0; }
    x0 += k1; x1 += ks2 + 1u;
    for (int i = 0; i < 4; i++) { x0 += x1; x1 = rotl32(x1, rb[i]); x1 ^= x0; }
    x0 += ks2; x1 += k0 + 2u;
    for (int i = 0; i < 4; i++) { x0 += x1; x1 = rotl32(x1, ra[i]); x1 ^= x0; }
    x0 += k0; x1 += k1 + 3u;
    for (int i = 0; i < 4; i++) { x0 += x1; x1 = rotl32(x1, rb[i]); x1 ^= x0; }
    x0 += k1; x1 += ks2 + 4u;
    for (int i = 0; i < 4; i++) { x0 += x1; x1 = rotl32(x1, ra[i]); x1 ^= x0; }
    x0 += ks2; x1 += k0 + 5u;
    o0 = x0; o1 = x1;
}

#if JAX_PARTITIONABLE
// fold-like split: child i = full cipher output of counter (hi=0, lo=i)
static KeyPair split_child(KeyPair k, uint32_t i, uint32_t /*num*/) {
    KeyPair r; tf2x32(k.a, k.b, 0u, i, r.a, r.b); return r;
}
// partitionable 32-bit random bits at flat index i: v0 ^ v1
static void bits64(KeyPair k, uint32_t* out /*64*/) {
    for (uint32_t i = 0; i < 64; i++) {
        uint32_t a, b; tf2x32(k.a, k.b, 0u, i, a, b);
        out[i] = a ^ b;
    }
}
#else
// original split: counts = iota(2*num) split into halves, out = [v0s..., v1s...]
static KeyPair split_child(KeyPair k, uint32_t i, uint32_t num) {
    // out[j] for j < num is cipher(j, j+num).v0 ; out[num+j] is .v1
    // key_i = (out[2i], out[2i+1])
    uint32_t out[16];
    for (uint32_t j = 0; j < num; j++) {
        uint32_t a, b; tf2x32(k.a, k.b, j, j + num, a, b);
        out[j] = a; out[num + j] = b;
    }
    KeyPair r; r.a = out[2 * i]; r.b = out[2 * i + 1]; return r;
}
static void bits64(KeyPair k, uint32_t* out /*64*/) {
    for (uint32_t i = 0; i < 32; i++) {
        uint32_t a, b; tf2x32(k.a, k.b, i, i + 32, a, b);
        out[i] = a; out[32 + i] = b;
    }
}
#endif

// jax.random.permutation(key, 64): one sort round (exponent-3 rule -> 1 round for n=64)
static void perm64(KeyPair key, int* out /*64*/) {
    // key, subkey = split(key); sort_keys = random_bits(subkey, 32, (64,))
    KeyPair sub = split_child(key, 1, 2);
    uint32_t sk[64]; int idx[64];
    bits64(sub, sk);
    for (int i = 0; i < 64; i++) idx[i] = i;
    std::stable_sort(idx, idx + 64, [&](int x, int y) { return sk[x] < sk[y]; });
    for (int i = 0; i < 64; i++) out[i] = idx[i];
}

static void compute_cols(ColsParam& cp) {
    KeyPair base{0u, 42u};                      // jax.random.key(42)
    KeyPair kc[2] = { split_child(base, 0, 2),  // k1 -> chain 0
                      split_child(base, 1, 2) };// k2 -> chain 1
    int p[64];
    for (int c = 0; c < 2; c++) {
        KeyPair K = kc[c];
        // sampling round k=0 (n=25): key, ka, kb = split(key, 3)
        KeyPair Kn = split_child(K, 0, 3);
        KeyPair ka = split_child(K, 1, 3);
        KeyPair kb = split_child(K, 2, 3);
        perm64(ka, p); for (int j = 0; j < 25; j++) cp.out25[c][j] = p[j];
        perm64(kb, p); for (int j = 0; j < 25; j++) cp.in25 [c][j] = p[j];
        // round k=1 (n=10)
        K = Kn;
        ka = split_child(K, 1, 3);
        kb = split_child(K, 2, 3);
        perm64(ka, p); for (int j = 0; j < 10; j++) cp.out10[c][j] = p[j];
        perm64(kb, p); for (int j = 0; j < 10; j++) cp.in10 [c][j] = p[j];
    }
}

} // namespace

// ---------------- kernels ----------------

// s1[c][b*50 + t] : t<25 -> out-neighbor cols, t>=25 -> in-neighbor cols
__global__ void k_sample(const int* __restrict__ nodes1, const int* __restrict__ nodes2,
                         const int* __restrict__ nout, const int* __restrict__ nin,
                         ColsParam cp) {
    int c = blockIdx.y, b = blockIdx.x, t = threadIdx.x; // t in [0,50)
    int v = (c ? nodes2 : nodes1)[b];
    int idx = (t < 25) ? nout[v * DEG + cp.out25[c][t]]
                       : nin [v * DEG + cp.in25 [c][t - 25]];
    g_s1[c][b * 50 + t] = idx;
}

// hop-1 aggregation: agg1[row] = [feat(self), mean10(out), mean10(in)]
__global__ __launch_bounds__(128) void k_agg_hop1(const int* __restrict__ nout,
                                                  const int* __restrict__ nin,
                                                  const float* __restrict__ feat,
                                                  ColsParam cp) {
    int c = blockIdx.y;
    int i = blockIdx.x;   // 0..S1N-1
    int f = threadIdx.x;  // 0..127
    __shared__ int nb[20];
    int s = g_s1[c][i];
    if (f < 10)       nb[f] = nout[s * DEG + cp.out10[c][f]];
    else if (f < 20)  nb[f] = nin [s * DEG + cp.in10 [c][f - 10]];
    __syncthreads();
    float self = feat[(size_t)s * FD + f];
    float so = 0.f, si = 0.f;
#pragma unroll
    for (int j = 0; j < 10; j++)  so += feat[(size_t)nb[j] * FD + f];
#pragma unroll
    for (int j = 10; j < 20; j++) si += feat[(size_t)nb[j] * FD + f];
    float* o = g_agg1 + ((size_t)c * S1N + i) * 384;
    o[f]        = self;
    o[128 + f]  = so / 10.0f;
    o[256 + f]  = si / 10.0f;
}

// hop-0 aggregation: agg0[c,b] = [feat(node), mean25(feat of s1 out), mean25(in)]
__global__ __launch_bounds__(128) void k_agg_hop0(const int* __restrict__ nodes1,
                                                  const int* __restrict__ nodes2,
                                                  const float* __restrict__ feat) {
    int c = blockIdx.y, b = blockIdx.x, f = threadIdx.x;
    int v = (c ? nodes2 : nodes1)[b];
    const int* s1 = &g_s1[c][b * 50];
    float self = feat[(size_t)v * FD + f];
    float so = 0.f, si = 0.f;
#pragma unroll 5
    for (int j = 0; j < 25; j++)  so += feat[(size_t)s1[j] * FD + f];
#pragma unroll 5
    for (int j = 25; j < 50; j++) si += feat[(size_t)s1[j] * FD + f];
    float* o = g_agg0 + (size_t)(c * BB + b) * 384;
    o[f]       = self;
    o[128 + f] = so / 25.0f;
    o[256 + f] = si / 25.0f;
}

// C[M,128] = sigmoid(A[M,384] @ W[384,128]);  BN=128, BK=16, 256 threads, BM = 8*TM
template <int BM, int TM>
__device__ __forceinline__ void sgemm_sig_body(const float* __restrict__ A,
                                               const float* __restrict__ W,
                                               float* __restrict__ C,
                                               int M, int bm) {
    __shared__ float sA[16][BM + 1];
    __shared__ float sB[16][128];
    int tid = threadIdx.x;
    int tx = tid & 31;   // col group: cols tx*4..tx*4+3
    int ty = tid >> 5;   // row group: rows ty*TM..
    float4 acc[TM];
#pragma unroll
    for (int i = 0; i < TM; i++) acc[i] = make_float4(0.f, 0.f, 0.f, 0.f);

    for (int k0 = 0; k0 < 384; k0 += 16) {
        if (tid < BM * 4) {
            int r = tid >> 2, kq = tid & 3;
            float4 v = *(const float4*)&A[(size_t)(bm + r) * 384 + k0 + kq * 4];
            sA[kq * 4 + 0][r] = v.x; sA[kq * 4 + 1][r] = v.y;
            sA[kq * 4 + 2][r] = v.z; sA[kq * 4 + 3][r] = v.w;
        }
        {
            int l = tid, kr = l >> 5, c4 = l & 31;
            *(float4*)&sB[kr][c4 * 4] = *(const float4*)&W[(size_t)(k0 + kr) * 128 + c4 * 4];
            l += 256; kr = l >> 5; c4 = l & 31;
            *(float4*)&sB[kr][c4 * 4] = *(const float4*)&W[(size_t)(k0 + kr) * 128 + c4 * 4];
        }
        __syncthreads();
#pragma unroll
        for (int kk = 0; kk < 16; kk++) {
            float4 bv = *(const float4*)&sB[kk][tx * 4];
#pragma unroll
            for (int i = 0; i < TM; i++) {
                float a = sA[kk][ty * TM + i];
                acc[i].x += a * bv.x; acc[i].y += a * bv.y;
                acc[i].z += a * bv.z; acc[i].w += a * bv.w;
            }
        }
        __syncthreads();
    }
#pragma unroll
    for (int i = 0; i < TM; i++) {
        int r = bm + ty * TM + i;
        if (r < M) {
            float4 v = acc[i];
            v.x = 1.f / (1.f + expf(-v.x));
            v.y = 1.f / (1.f + expf(-v.y));
            v.z = 1.f / (1.f + expf(-v.z));
            v.w = 1.f / (1.f + expf(-v.w));
            *(float4*)&C[(size_t)r * 128 + tx * 4] = v;
        }
    }
}

__global__ __launch_bounds__(256) void k_gemm_h1(const float* __restrict__ W) {
    sgemm_sig_body<64, 8>(g_agg1, W, g_h1, M1, blockIdx.x * 64);
}
__global__ __launch_bounds__(256) void k_gemm_h0(const float* __restrict__ W) {
    sgemm_sig_body<16, 2>(g_agg0, W, g_h0, 2 * BB, blockIdx.x * 16);
}
__global__ __launch_bounds__(256) void k_gemm_heads(const float* __restrict__ Wm,
                                                    const float* __restrict__ Ws,
                                                    const float* __restrict__ Wp) {
    const float* W = (blockIdx.z == 0) ? Wm : (blockIdx.z == 1) ? Ws : Wp;
    sgemm_sig_body<16, 2>(g_aggL1, W, g_head[blockIdx.z], 2 * BB, blockIdx.x * 16);
}

// layer-1 aggregation: aggL1[c,b] = [h0, mean25(h1 rows 0..24), mean25(25..49)]
__global__ __launch_bounds__(128) void k_aggL1() {
    int c = blockIdx.y, b = blockIdx.x, f = threadIdx.x;
    const float* h1 = g_h1 + (size_t)(c * S1N + b * 50) * 128;
    float self = g_h0[(size_t)(c * BB + b) * 128 + f];
    float s0 = 0.f, s1v = 0.f;
#pragma unroll 5
    for (int j = 0; j < 25; j++)  s0  += h1[(size_t)j * 128 + f];
#pragma unroll 5
    for (int j = 25; j < 50; j++) s1v += h1[(size_t)j * 128 + f];
    float* o = g_aggL1 + (size_t)(c * BB + b) * 384;
    o[f]       = self;
    o[128 + f] = s0  / 25.0f;
    o[256 + f] = s1v / 25.0f;
}

// out[slot, b, d] = g_head[head][chain*256 + b] @ Wd_head ; slot = chain*3 + head
__global__ __launch_bounds__(256) void k_final(const float* __restrict__ Wm,
                                               const float* __restrict__ Ws,
                                               const float* __restrict__ Wp,
                                               float* __restrict__ out) {
    __shared__ float sW[128 * 64];
    __shared__ float sH[16 * 128];
    int slot = blockIdx.x, rt = blockIdx.y, tid = threadIdx.x;
    int chain = slot / 3, head = slot % 3;
    const float* Wd = (head == 0) ? Wm : (head == 1) ? Ws : Wp;
    const float* H = &g_head[head][(size_t)(chain * BB + rt * 16) * 128];
    for (int l = tid; l < 128 * 64; l += 256) sW[l] = Wd[l];
    for (int l = tid; l < 16 * 128; l += 256) sH[l] = H[l];
    __syncthreads();
    int d = tid & 63, rg = tid >> 6;
#pragma unroll
    for (int ii = 0; ii < 4; ii++) {
        int r = rg * 4 + ii;
        float acc = 0.f;
#pragma unroll 8
        for (int k = 0; k < 128; k++) acc += sH[r * 128 + k] * sW[k * 64 + d];
        out[((size_t)slot * BB + rt * 16 + r) * 64 + d] = acc;
    }
}

// ---------------- launcher ----------------
extern "C" void kernel_launch(void* const* d_in, const int* in_sizes, int n_in,
                              void* d_out, int out_size) {
    (void)in_sizes; (void)n_in; (void)out_size;
    const int*   nodes1 = (const int*)  d_in[0];
    const int*   nodes2 = (const int*)  d_in[1];
    const int*   nout   = (const int*)  d_in[2];
    const int*   nin    = (const int*)  d_in[3];
    const float* feat   = (const float*)d_in[4];
    const float* W_in   = (const float*)d_in[5];
    const float* W_mean = (const float*)d_in[6];
    const float* W_std  = (const float*)d_in[7];
    const float* W_pi   = (const float*)d_in[8];
    // d_in[9] = W_ag, d_in[10] = W_ad : unused by the reference forward
    const float* Wd_mean = (const float*)d_in[11];
    const float* Wd_std  = (const float*)d_in[12];
    const float* Wd_pi   = (const float*)d_in[13];
    float* out = (float*)d_out;

    ColsParam cp;
    compute_cols(cp);   // deterministic constants (seed 42), recomputed each call

    k_sample  <<<dim3(BB, 2),   50>>>(nodes1, nodes2, nout, nin, cp);
    k_agg_hop1<<<dim3(S1N, 2), 128>>>(nout, nin, feat, cp);
    k_agg_hop0<<<dim3(BB, 2),  128>>>(nodes1, nodes2, feat);
    k_gemm_h1 <<<M1 / 64, 256>>>(W_in);
    k_gemm_h0 <<<(2 * BB) / 16, 256>>>(W_in);
    k_aggL1   <<<dim3(BB, 2), 128>>>();
    k_gemm_heads<<<dim3((2 * BB) / 16, 1, 3), 256>>>(W_mean, W_std, W_pi);
    k_final   <<<dim3(6, BB / 16), 256>>>(Wd_mean, Wd_std, Wd_pi, out);
}